// round 8
// baseline (speedup 1.0000x reference)
#include <cuda_runtime.h>
#include <cuda_bf16.h>

#define SIDE 9
#define STATE 81
#define NA 5
#define H 32
#define WARPS_K1 8

#define K2_THREADS 256
#define K2_ROWS    64        // 4 threads per row
#define H1_STRIDE  36

// ---------------------------------------------------------------------------
// K1: warp-per-row scatter + reward (round-2 proven form).
// ---------------------------------------------------------------------------
__global__ __launch_bounds__(32 * WARPS_K1) void k1_nsc_reward(
    const float* __restrict__ obs,          // (B, 3*STATE)
    const float* __restrict__ acr_g,        // (B, STATE*NA)
    float* __restrict__ out,                // [sym(B), imm(B), ret(B), nsc(B*81)]
    int B)
{
    __shared__ float s[WARPS_K1][416];

    const int wid  = threadIdx.x >> 5;
    const int lane = threadIdx.x & 31;
    const long long row = (long long)blockIdx.x * WARPS_K1 + wid;
    if (row >= B) return;

    const float* __restrict__ acr = acr_g + row * (STATE * NA);
    float* __restrict__ sp = s[wid];
    #pragma unroll
    for (int k = 0; k < 13; k++) {
        const int i = lane + 32 * k;
        if (i < STATE * NA) sp[i] = __ldg(&acr[i]);
    }
    __syncwarp();

    const float* __restrict__ dem = obs + row * (3 * STATE) + 2 * STATE;
    float* __restrict__ nout = out + 3LL * B + row * STATE;

    float imm = 0.0f;
    #pragma unroll
    for (int k = 0; k < 3; k++) {
        const int c = lane + 32 * k;
        if (c < STATE) {
            const int r   = c / SIDE;
            const int col = c - r * SIDE;
            float v = sp[c * NA + 0];
            if (r == 0)        v += sp[c * NA + 1];
            if (r < SIDE - 1)  v += sp[(c + SIDE) * NA + 1];
            if (r == SIDE - 1) v += sp[c * NA + 2];
            if (r > 0)         v += sp[(c - SIDE) * NA + 2];
            if (col == 0)      v += sp[c * NA + 3];
            if (col < SIDE - 1)v += sp[(c + 1) * NA + 3];
            if (col == SIDE-1) v += sp[c * NA + 4];
            if (col > 0)       v += sp[(c - 1) * NA + 4];

            nout[c] = v;
            imm += fminf(v, __ldg(&dem[c]));
        }
    }

    #pragma unroll
    for (int o = 16; o; o >>= 1) imm += __shfl_xor_sync(0xffffffffu, imm, o);
    if (lane == 0) out[(long long)B + row] = imm;
}

// ---------------------------------------------------------------------------
// Packed f32x2 helpers (sm_103a FFMA2)
// ---------------------------------------------------------------------------
__device__ __forceinline__ unsigned long long pack2(float x) {
    unsigned long long r;
    asm("mov.b64 %0, {%1, %1};" : "=l"(r) : "f"(x));
    return r;
}
__device__ __forceinline__ void ffma2(unsigned long long& d,
                                      unsigned long long a,
                                      unsigned long long b) {
    asm("fma.rn.f32x2 %0, %1, %2, %0;" : "+l"(d) : "l"(a), "l"(b));
}
__device__ __forceinline__ void unpack2(unsigned long long p, float& lo, float& hi) {
    asm("mov.b64 {%0, %1}, %2;" : "=f"(lo), "=f"(hi) : "l"(p));
}

// ---------------------------------------------------------------------------
// K2: 4 threads per row, 8 columns per thread. 44.6KB static smem, ~8-reg
// accumulators -> 4-5 blocks/SM (32-40 warps). All LDS conflict-free.
// ---------------------------------------------------------------------------
__global__ __launch_bounds__(K2_THREADS, 4) void k2_mlp(
    const float* __restrict__ W1,
    const float* __restrict__ W2,
    const float* __restrict__ W3,
    const float* __restrict__ b3,
    float* __restrict__ out,
    int B)
{
    __shared__ float s_nsc[K2_ROWS * STATE];      // 20.7 KB
    __shared__ float s_h1[K2_ROWS * H1_STRIDE];   //  9.2 KB
    __shared__ float sW1[STATE * H];              // 10.4 KB
    __shared__ float sW2[H * H];                  //  4.0 KB
    __shared__ float sW3[H];
    __shared__ float sb3;

    const int tid = threadIdx.x;
    for (int i = tid; i < STATE * H; i += K2_THREADS) sW1[i] = W1[i];
    for (int i = tid; i < H * H; i += K2_THREADS)     sW2[i] = W2[i];
    if (tid < H)  sW3[tid] = W3[tid];
    if (tid == 0) sb3 = b3[0];

    const long long blockRow0 = (long long)blockIdx.x * K2_ROWS;
    const float* __restrict__ nsc_g = out + 3LL * B;

    // Block-wide coalesced float4 stage of 64 contiguous rows (5184 floats).
    if (blockRow0 + K2_ROWS <= B) {
        const float4* __restrict__ src =
            reinterpret_cast<const float4*>(nsc_g + blockRow0 * STATE);
        float4* __restrict__ dst = reinterpret_cast<float4*>(s_nsc);
        #pragma unroll
        for (int i = tid; i < K2_ROWS * STATE / 4; i += K2_THREADS)
            dst[i] = __ldg(&src[i]);
    } else {
        for (int i = tid; i < K2_ROWS * STATE; i += K2_THREADS) {
            const long long gi = blockRow0 * STATE + i;
            if (gi < (long long)B * STATE) s_nsc[i] = nsc_g[gi];
        }
    }
    __syncthreads();

    const int r = tid >> 2;              // row within block (warp owns rows 8w..8w+7)
    const int g = tid & 3;               // column group: cols 8g..8g+7
    const long long b = blockRow0 + r;

    const float* __restrict__ myn = s_nsc + r * STATE;

    // ---- Layer 1: 8 columns per thread (4 f32x2 accumulators) ----
    unsigned long long a0 = 0ULL, a1 = 0ULL, a2 = 0ULL, a3 = 0ULL;
    #pragma unroll 27
    for (int d = 0; d < STATE; d++) {
        const unsigned long long v = pack2(myn[d]);
        const ulonglong2 wA =
            *reinterpret_cast<const ulonglong2*>(&sW1[d * H + 8 * g]);
        const ulonglong2 wB =
            *reinterpret_cast<const ulonglong2*>(&sW1[d * H + 8 * g + 4]);
        ffma2(a0, v, wA.x);
        ffma2(a1, v, wA.y);
        ffma2(a2, v, wB.x);
        ffma2(a3, v, wB.y);
    }

    // ReLU + publish 8 h1 values (2x STS.128, stride 36 -> at most 2-way).
    {
        float x0, x1, x2, x3, x4, x5, x6, x7;
        unpack2(a0, x0, x1); unpack2(a1, x2, x3);
        unpack2(a2, x4, x5); unpack2(a3, x6, x7);
        float4 hA = make_float4(fmaxf(x0,0.f), fmaxf(x1,0.f),
                                fmaxf(x2,0.f), fmaxf(x3,0.f));
        float4 hB = make_float4(fmaxf(x4,0.f), fmaxf(x5,0.f),
                                fmaxf(x6,0.f), fmaxf(x7,0.f));
        *reinterpret_cast<float4*>(&s_h1[r * H1_STRIDE + 8 * g])     = hA;
        *reinterpret_cast<float4*>(&s_h1[r * H1_STRIDE + 8 * g + 4]) = hB;
    }
    __syncwarp();   // row r's 4 producers == its 4 consumers, same warp

    // ---- Layer 2: 8 columns per thread ----
    unsigned long long z0 = 0ULL, z1 = 0ULL, z2 = 0ULL, z3 = 0ULL;
    const float* __restrict__ myh = s_h1 + r * H1_STRIDE;
    #pragma unroll
    for (int i = 0; i < H; i++) {
        const unsigned long long v = pack2(myh[i]);
        const ulonglong2 wA =
            *reinterpret_cast<const ulonglong2*>(&sW2[i * H + 8 * g]);
        const ulonglong2 wB =
            *reinterpret_cast<const ulonglong2*>(&sW2[i * H + 8 * g + 4]);
        ffma2(z0, v, wA.x);
        ffma2(z1, v, wA.y);
        ffma2(z2, v, wB.x);
        ffma2(z3, v, wB.y);
    }

    // ---- Layer 3 partial + reduce over the 4 column threads ----
    float part;
    {
        float x0, x1, x2, x3, x4, x5, x6, x7;
        unpack2(z0, x0, x1); unpack2(z1, x2, x3);
        unpack2(z2, x4, x5); unpack2(z3, x6, x7);
        const float4 wA = *reinterpret_cast<const float4*>(&sW3[8 * g]);
        const float4 wB = *reinterpret_cast<const float4*>(&sW3[8 * g + 4]);
        part  = fmaxf(x0, 0.f) * wA.x;
        part += fmaxf(x1, 0.f) * wA.y;
        part += fmaxf(x2, 0.f) * wA.z;
        part += fmaxf(x3, 0.f) * wA.w;
        part += fmaxf(x4, 0.f) * wB.x;
        part += fmaxf(x5, 0.f) * wB.y;
        part += fmaxf(x6, 0.f) * wB.z;
        part += fmaxf(x7, 0.f) * wB.w;
    }
    part += __shfl_xor_sync(0xffffffffu, part, 1);
    part += __shfl_xor_sync(0xffffffffu, part, 2);

    if (g == 0 && b < B) {
        const float ret = part + sb3;
        const float imm = out[(long long)B + b];
        out[b]                      = imm + ret;  // symbolic_val
        out[2LL * (long long)B + b] = ret;        // next_return
    }
}

extern "C" void kernel_launch(void* const* d_in, const int* in_sizes, int n_in,
                              void* d_out, int out_size) {
    const float* obs = (const float*)d_in[0];
    const float* action_count = (const float*)d_in[1];
    const float* W1 = (const float*)d_in[2];
    const float* W2 = (const float*)d_in[3];
    const float* W3 = (const float*)d_in[4];
    const float* b3 = (const float*)d_in[5];
    float* out = (float*)d_out;

    const int B = in_sizes[0] / (3 * STATE);

    const int blocks1 = (B + WARPS_K1 - 1) / WARPS_K1;
    k1_nsc_reward<<<blocks1, 32 * WARPS_K1>>>(obs, action_count, out, B);

    const int blocks2 = (B + K2_ROWS - 1) / K2_ROWS;
    k2_mlp<<<blocks2, K2_THREADS>>>(W1, W2, W3, b3, out, B);
}

// round 9
// speedup vs baseline: 1.2054x; 1.2054x over previous
#include <cuda_runtime.h>
#include <cuda_bf16.h>

#define SIDE 9
#define STATE 81
#define NA 5
#define H 32
#define WARPS_K1 8
#define MAX_B 131072

// nsc transposed scratch: [d][b]
__device__ float g_nscT[(size_t)STATE * MAX_B];

// ---------------------------------------------------------------------------
// K1: warp-per-row scatter + reward + transposed scratch write (round-7 form).
// ---------------------------------------------------------------------------
__global__ __launch_bounds__(32 * WARPS_K1) void k1_nsc_reward(
    const float* __restrict__ obs,          // (B, 3*STATE)
    const float* __restrict__ acr_g,        // (B, STATE*NA)
    float* __restrict__ out,                // [sym(B), imm(B), ret(B), nsc(B*81)]
    int B)
{
    __shared__ float s_ac[WARPS_K1][416];
    __shared__ float s_nsc[WARPS_K1 * STATE];

    const int tid  = threadIdx.x;
    const int wid  = tid >> 5;
    const int lane = tid & 31;
    const long long row0 = (long long)blockIdx.x * WARPS_K1;
    const long long row  = row0 + wid;

    if (row < B) {
        const float* __restrict__ acr = acr_g + row * (STATE * NA);
        float* __restrict__ sp = s_ac[wid];
        #pragma unroll
        for (int k = 0; k < 13; k++) {
            const int i = lane + 32 * k;
            if (i < STATE * NA) sp[i] = __ldg(&acr[i]);
        }
        __syncwarp();

        const float* __restrict__ dem = obs + row * (3 * STATE) + 2 * STATE;
        float* __restrict__ nout = out + 3LL * B + row * STATE;
        float* __restrict__ nrow = s_nsc + wid * STATE;

        float imm = 0.0f;
        #pragma unroll
        for (int k = 0; k < 3; k++) {
            const int c = lane + 32 * k;
            if (c < STATE) {
                const int r   = c / SIDE;
                const int col = c - r * SIDE;
                float v = sp[c * NA + 0];
                if (r == 0)        v += sp[c * NA + 1];
                if (r < SIDE - 1)  v += sp[(c + SIDE) * NA + 1];
                if (r == SIDE - 1) v += sp[c * NA + 2];
                if (r > 0)         v += sp[(c - SIDE) * NA + 2];
                if (col == 0)      v += sp[c * NA + 3];
                if (col < SIDE - 1)v += sp[(c + 1) * NA + 3];
                if (col == SIDE-1) v += sp[c * NA + 4];
                if (col > 0)       v += sp[(c - 1) * NA + 4];

                nout[c] = v;                      // gmem, coalesced
                nrow[c] = v;                      // smem
                imm += fminf(v, __ldg(&dem[c]));
            }
        }

        #pragma unroll
        for (int o = 16; o; o >>= 1) imm += __shfl_xor_sync(0xffffffffu, imm, o);
        if (lane == 0) out[(long long)B + row] = imm;
    }
    __syncthreads();

    // Transposed write: g_nscT[d*B + row0 + j] = s_nsc[j*81 + d]
    for (int i = tid; i < STATE * WARPS_K1; i += 32 * WARPS_K1) {
        const int d = i >> 3;
        const int j = i & 7;
        if (row0 + j < B)
            g_nscT[(long long)d * B + row0 + j] = s_nsc[j * STATE + d];
    }
}

// ---------------------------------------------------------------------------
// Packed f32x2 helpers (sm_103a FFMA2)
// ---------------------------------------------------------------------------
__device__ __forceinline__ unsigned long long pack2(float x) {
    unsigned long long r;
    asm("mov.b64 %0, {%1, %1};" : "=l"(r) : "f"(x));
    return r;
}
__device__ __forceinline__ void ffma2(unsigned long long& d,
                                      unsigned long long a,
                                      unsigned long long b) {
    asm("fma.rn.f32x2 %0, %1, %2, %0;" : "+l"(d) : "l"(a), "l"(b));
}
__device__ __forceinline__ void unpack2(unsigned long long p, float& lo, float& hi) {
    asm("mov.b64 {%0, %1}, %2;" : "=f"(lo), "=f"(hi) : "l"(p));
}

// ---------------------------------------------------------------------------
// K2: 2 threads per row, 16 columns per thread. nsc streamed coalesced from
// transposed scratch (no nsc smem!). Weight LDS have only 2 distinct
// addresses/warp (dedup -> 1 wavefront). ~50 live regs -> 4 blocks/SM.
// ---------------------------------------------------------------------------
__global__ __launch_bounds__(256, 4) void k2_mlp(
    const float* __restrict__ W1,
    const float* __restrict__ W2,
    const float* __restrict__ W3,
    const float* __restrict__ b3,
    float* __restrict__ out,
    int B)
{
    __shared__ float sW1[STATE * H];   // 10.4 KB
    __shared__ float sW2[H * H];       //  4.0 KB
    __shared__ float sW3[H];
    __shared__ float sb3;

    for (int i = threadIdx.x; i < STATE * H; i += 256) sW1[i] = W1[i];
    for (int i = threadIdx.x; i < H * H; i += 256)     sW2[i] = W2[i];
    if (threadIdx.x < H)  sW3[threadIdx.x] = W3[threadIdx.x];
    if (threadIdx.x == 0) sb3 = b3[0];
    __syncthreads();

    const long long idx = (long long)blockIdx.x * 256 + threadIdx.x;
    long long b = idx >> 1;            // row
    const int g = (int)(idx & 1);      // column half: cols 16g..16g+15
    const bool valid = (b < B);
    if (b >= B) b = B - 1;             // clamp loads; writes guarded

    // ---- Layer 1: 16 cols/thread, 8 f32x2 accumulators ----
    unsigned long long a0=0, a1=0, a2=0, a3=0, a4=0, a5=0, a6=0, a7=0;
    #pragma unroll 9
    for (int d = 0; d < STATE; d++) {
        const unsigned long long v = pack2(__ldg(&g_nscT[(long long)d * B + b]));
        const ulonglong2* __restrict__ wp =
            reinterpret_cast<const ulonglong2*>(&sW1[d * H + 16 * g]);
        const ulonglong2 wA = wp[0], wB = wp[1];
        ffma2(a0, v, wA.x); ffma2(a1, v, wA.y);
        ffma2(a2, v, wB.x); ffma2(a3, v, wB.y);
    }
    // note: 16 floats need 4x16B; wp[2], wp[3]:
    #pragma unroll 9
    for (int d = 0; d < STATE; d++) {
        const unsigned long long v = pack2(__ldg(&g_nscT[(long long)d * B + b]));
        const ulonglong2* __restrict__ wp =
            reinterpret_cast<const ulonglong2*>(&sW1[d * H + 16 * g]);
        const ulonglong2 wC = wp[2], wD = wp[3];
        ffma2(a4, v, wC.x); ffma2(a5, v, wC.y);
        ffma2(a6, v, wD.x); ffma2(a7, v, wD.y);
    }

    // ReLU -> 16 own h1 values (cols 16g..16g+15)
    float h1f[16];
    {
        float lo, hi;
        unpack2(a0, lo, hi); h1f[0]=fmaxf(lo,0.f);  h1f[1]=fmaxf(hi,0.f);
        unpack2(a1, lo, hi); h1f[2]=fmaxf(lo,0.f);  h1f[3]=fmaxf(hi,0.f);
        unpack2(a2, lo, hi); h1f[4]=fmaxf(lo,0.f);  h1f[5]=fmaxf(hi,0.f);
        unpack2(a3, lo, hi); h1f[6]=fmaxf(lo,0.f);  h1f[7]=fmaxf(hi,0.f);
        unpack2(a4, lo, hi); h1f[8]=fmaxf(lo,0.f);  h1f[9]=fmaxf(hi,0.f);
        unpack2(a5, lo, hi); h1f[10]=fmaxf(lo,0.f); h1f[11]=fmaxf(hi,0.f);
        unpack2(a6, lo, hi); h1f[12]=fmaxf(lo,0.f); h1f[13]=fmaxf(hi,0.f);
        unpack2(a7, lo, hi); h1f[14]=fmaxf(lo,0.f); h1f[15]=fmaxf(hi,0.f);
    }

    // ---- Layer 2: z[16 own cols] over all 32 h1 (partner's via shfl) ----
    unsigned long long z0=0, z1=0, z2=0, z3=0, z4=0, z5=0, z6=0, z7=0;
    const int rowOwn = 16 * g;         // my h1 indices start
    const int rowOth = 16 - 16 * g;    // partner's start
    #pragma unroll
    for (int k = 0; k < 16; k++) {
        const float mine   = h1f[k];
        const float theirs = __shfl_xor_sync(0xffffffffu, mine, 1);
        const unsigned long long hm = pack2(mine);
        const unsigned long long ht = pack2(theirs);
        const ulonglong2* __restrict__ wm =
            reinterpret_cast<const ulonglong2*>(&sW2[(rowOwn + k) * H + 16 * g]);
        const ulonglong2* __restrict__ wt =
            reinterpret_cast<const ulonglong2*>(&sW2[(rowOth + k) * H + 16 * g]);
        ulonglong2 m0 = wm[0], m1 = wm[1], t0 = wt[0], t1 = wt[1];
        ffma2(z0, hm, m0.x); ffma2(z1, hm, m0.y);
        ffma2(z2, hm, m1.x); ffma2(z3, hm, m1.y);
        ffma2(z0, ht, t0.x); ffma2(z1, ht, t0.y);
        ffma2(z2, ht, t1.x); ffma2(z3, ht, t1.y);
        ulonglong2 m2 = wm[2], m3 = wm[3], t2 = wt[2], t3 = wt[3];
        ffma2(z4, hm, m2.x); ffma2(z5, hm, m2.y);
        ffma2(z6, hm, m3.x); ffma2(z7, hm, m3.y);
        ffma2(z4, ht, t2.x); ffma2(z5, ht, t2.y);
        ffma2(z6, ht, t3.x); ffma2(z7, ht, t3.y);
    }

    // ---- Layer 3 partial over 16 own cols + pair reduce ----
    float part = 0.0f;
    {
        const float* w3 = &sW3[16 * g];
        float lo, hi;
        unpack2(z0, lo, hi); part += fmaxf(lo,0.f)*w3[0]  + fmaxf(hi,0.f)*w3[1];
        unpack2(z1, lo, hi); part += fmaxf(lo,0.f)*w3[2]  + fmaxf(hi,0.f)*w3[3];
        unpack2(z2, lo, hi); part += fmaxf(lo,0.f)*w3[4]  + fmaxf(hi,0.f)*w3[5];
        unpack2(z3, lo, hi); part += fmaxf(lo,0.f)*w3[6]  + fmaxf(hi,0.f)*w3[7];
        unpack2(z4, lo, hi); part += fmaxf(lo,0.f)*w3[8]  + fmaxf(hi,0.f)*w3[9];
        unpack2(z5, lo, hi); part += fmaxf(lo,0.f)*w3[10] + fmaxf(hi,0.f)*w3[11];
        unpack2(z6, lo, hi); part += fmaxf(lo,0.f)*w3[12] + fmaxf(hi,0.f)*w3[13];
        unpack2(z7, lo, hi); part += fmaxf(lo,0.f)*w3[14] + fmaxf(hi,0.f)*w3[15];
    }
    part += __shfl_xor_sync(0xffffffffu, part, 1);

    if (g == 0 && valid) {
        const float ret = part + sb3;
        const float imm = __ldg(&out[(long long)B + b]);
        out[b]                      = imm + ret;  // symbolic_val
        out[2LL * (long long)B + b] = ret;        // next_return
    }
}

extern "C" void kernel_launch(void* const* d_in, const int* in_sizes, int n_in,
                              void* d_out, int out_size) {
    const float* obs = (const float*)d_in[0];
    const float* action_count = (const float*)d_in[1];
    const float* W1 = (const float*)d_in[2];
    const float* W2 = (const float*)d_in[3];
    const float* W3 = (const float*)d_in[4];
    const float* b3 = (const float*)d_in[5];
    float* out = (float*)d_out;

    const int B = in_sizes[0] / (3 * STATE);

    const int blocks1 = (B + WARPS_K1 - 1) / WARPS_K1;
    k1_nsc_reward<<<blocks1, 32 * WARPS_K1>>>(obs, action_count, out, B);

    const long long totalThreads = 2LL * B;
    const int blocks2 = (int)((totalThreads + 255) / 256);
    k2_mlp<<<blocks2, 256>>>(W1, W2, W3, b3, out, B);
}